// round 7
// baseline (speedup 1.0000x reference)
#include <cuda_runtime.h>
#include <stdint.h>

#define N_RAYS   1048576
#define N_LEVELS 6
#define HASHMAP_SIZE (1u << 19)
#define HASH_MASK    (HASHMAP_SIZE - 1u)
#define SPHERE_R 500.0f

#define OCT_RES   512                      // 2D octahedral bins per axis
#define NBINS     (OCT_RES * OCT_RES)      // 262144
#define SCAN_CHUNK 2048
#define SCAN_BLOCKS (NBINS / SCAN_CHUNK)   // 128

__device__ uint32_t d_hist[NBINS];
__device__ uint32_t d_offsets[NBINS];      // chunk-local after k2a
__device__ uint32_t d_bsum[SCAN_BLOCKS];
__device__ float4   d_coords[N_RAYS];
__device__ uint32_t d_bin[N_RAYS];
__device__ uint32_t d_perm[N_RAYS];

// ---------------------------------------------------------------- helpers
__device__ __forceinline__ uint32_t expand2(uint32_t v)
{
    v &= 0xFFFFu;
    v = (v | (v << 8)) & 0x00FF00FFu;
    v = (v | (v << 4)) & 0x0F0F0F0Fu;
    v = (v | (v << 2)) & 0x33333333u;
    v = (v | (v << 1)) & 0x55555555u;
    return v;
}

__device__ __forceinline__ float3 ray_coords(const float* __restrict__ dirs,
                                             const float* __restrict__ origs, int i)
{
    const float dx = dirs[3 * i + 0], dy = dirs[3 * i + 1], dz = dirs[3 * i + 2];
    const float ox = origs[3 * i + 0], oy = origs[3 * i + 1], oz = origs[3 * i + 2];
    float b    = 2.0f * (ox * dx + oy * dy + oz * dz);
    float c    = (ox * ox + oy * oy + oz * oz) - SPHERE_R * SPHERE_R;
    float disc = b * b - 4.0f * c;
    float t    = 0.5f * (sqrtf(fmaxf(disc, 0.0f)) - b);
    const float inv2R = 1.0f / (2.0f * SPHERE_R);
    float3 r;
    r.x = fminf(fmaxf((ox + t * dx + SPHERE_R) * inv2R, 0.0f), 1.0f);
    r.y = fminf(fmaxf((oy + t * dy + SPHERE_R) * inv2R, 0.0f), 1.0f);
    r.z = fminf(fmaxf((oz + t * dz + SPHERE_R) * inv2R, 0.0f), 1.0f);
    return r;
}

__device__ __forceinline__ void stcs_f4(float4* p, float4 v)
{
    asm volatile("st.global.cs.v4.f32 [%0], {%1,%2,%3,%4};"
                 :: "l"(p), "f"(v.x), "f"(v.y), "f"(v.z), "f"(v.w) : "memory");
}
__device__ __forceinline__ void stcs_u32(uint32_t* p, uint32_t v)
{
    asm volatile("st.global.cs.u32 [%0], %1;" :: "l"(p), "r"(v) : "memory");
}
__device__ __forceinline__ float4 ldcs_f4(const float4* p)
{
    float4 v;
    asm volatile("ld.global.cs.v4.f32 {%0,%1,%2,%3}, [%4];"
                 : "=f"(v.x), "=f"(v.y), "=f"(v.z), "=f"(v.w) : "l"(p));
    return v;
}

// ---------------------------------------------------------------- K0: zero hist (1 MB)
__global__ void k0_zero()
{
    int i = blockIdx.x * blockDim.x + threadIdx.x;
    reinterpret_cast<uint4*>(d_hist)[i] = make_uint4(0u, 0u, 0u, 0u);
}

// ---------------------------------------------------------------- K1: coords + octahedral Morton bin + histogram
__global__ void __launch_bounds__(256)
k1_bin(const float* __restrict__ dirs, const float* __restrict__ origs, int n)
{
    int i = blockIdx.x * blockDim.x + threadIdx.x;
    if (i >= n) return;
    float3 cc = ray_coords(dirs, origs, i);

    // unit direction (points lie exactly on the sphere)
    float px = 2.0f * cc.x - 1.0f;
    float py = 2.0f * cc.y - 1.0f;
    float pz = 2.0f * cc.z - 1.0f;
    float inv = 1.0f / (fabsf(px) + fabsf(py) + fabsf(pz));
    float u = px * inv, v = py * inv;
    if (pz < 0.0f) {
        float uu = (1.0f - fabsf(v)) * copysignf(1.0f, u);
        float vv = (1.0f - fabsf(u)) * copysignf(1.0f, v);
        u = uu; v = vv;
    }
    uint32_t bu = min((uint32_t)((u * 0.5f + 0.5f) * (float)OCT_RES), (uint32_t)(OCT_RES - 1));
    uint32_t bv = min((uint32_t)((v * 0.5f + 0.5f) * (float)OCT_RES), (uint32_t)(OCT_RES - 1));
    uint32_t bin = expand2(bu) | (expand2(bv) << 1);   // 18-bit Morton

    stcs_f4(&d_coords[i], make_float4(cc.x, cc.y, cc.z, 0.0f));
    stcs_u32(&d_bin[i], bin);
    atomicAdd(&d_hist[bin], 1u);
}

// ---------------------------------------------------------------- block scan helper (1024 threads)
__device__ __forceinline__ uint32_t block_incl_scan_1024(uint32_t v, uint32_t* wsum)
{
    const int lane = threadIdx.x & 31, wid = threadIdx.x >> 5;
    uint32_t x = v;
#pragma unroll
    for (int d = 1; d < 32; d <<= 1) {
        uint32_t y = __shfl_up_sync(0xffffffffu, x, d);
        if (lane >= d) x += y;
    }
    if (lane == 31) wsum[wid] = x;
    __syncthreads();
    if (wid == 0) {
        uint32_t s = wsum[lane];
        uint32_t t = s;
#pragma unroll
        for (int d = 1; d < 32; d <<= 1) {
            uint32_t y = __shfl_up_sync(0xffffffffu, t, d);
            if (lane >= d) t += y;
        }
        wsum[lane] = t - s;
    }
    __syncthreads();
    return x + wsum[wid];
}

// ---------------------------------------------------------------- K2a: per-chunk scan (chunk-local offsets)
__global__ void __launch_bounds__(1024)
k2a_scan()
{
    __shared__ uint32_t wsum[32];
    const int base = blockIdx.x * SCAN_CHUNK;
    const int t = threadIdx.x;
    uint2 e = reinterpret_cast<const uint2*>(d_hist + base)[t];
    uint32_t s = e.x + e.y;
    uint32_t incl = block_incl_scan_1024(s, wsum);
    uint32_t excl = incl - s;
    reinterpret_cast<uint2*>(d_offsets + base)[t] = make_uint2(excl, excl + e.x);
    if (t == 1023) d_bsum[blockIdx.x] = incl;
}

// ---------------------------------------------------------------- K2b: exclusive scan of 128 chunk sums
__global__ void __launch_bounds__(128)
k2b_scan()
{
    __shared__ uint32_t wsum[4];
    const int lane = threadIdx.x & 31, wid = threadIdx.x >> 5;
    uint32_t v = d_bsum[threadIdx.x];
    uint32_t x = v;
#pragma unroll
    for (int d = 1; d < 32; d <<= 1) {
        uint32_t y = __shfl_up_sync(0xffffffffu, x, d);
        if (lane >= d) x += y;
    }
    if (lane == 31) wsum[wid] = x;
    __syncthreads();
    uint32_t add = 0;
#pragma unroll
    for (int k = 0; k < 4; ++k)
        if (k < wid) add += wsum[k];
    d_bsum[threadIdx.x] = x - v + add;   // exclusive
}

// ---------------------------------------------------------------- K3: build permutation (adds chunk base)
__global__ void __launch_bounds__(256)
k3_scatter(int n)
{
    int i = blockIdx.x * blockDim.x + threadIdx.x;
    if (i >= n) return;
    uint32_t bin = d_bin[i];
    uint32_t pos = atomicAdd(&d_offsets[bin], 1u) + __ldg(&d_bsum[bin / SCAN_CHUNK]);
    stcs_u32(&d_perm[pos], (uint32_t)i);
}

// ---------------------------------------------------------------- K4: pipelined coherent encode
template<int L>
__device__ __forceinline__ void level_idx(float cx, float cy, float cz,
                                          uint32_t* idx, float3& w)
{
    const float scale = (float)((16 << L) - 1);
    float px = cx * scale + 0.5f;
    float py = cy * scale + 0.5f;
    float pz = cz * scale + 0.5f;
    float fx = floorf(px), fy = floorf(py), fz = floorf(pz);
    w.x = px - fx; w.y = py - fy; w.z = pz - fz;
    uint32_t gx = (uint32_t)fx, gy = (uint32_t)fy, gz = (uint32_t)fz;

    if (L < 3) {
        const uint32_t r  = 16u << L;
        const uint32_t rm = r - 1u;
        uint32_t x0 = gx,            x1 = min(gx + 1u, rm);
        uint32_t y0 = gy * r,        y1 = min(gy + 1u, rm) * r;
        uint32_t z0 = gz * r * r,    z1 = min(gz + 1u, rm) * r * r;
        idx[0] = x0 + y0 + z0; idx[1] = x1 + y0 + z0;
        idx[2] = x0 + y1 + z0; idx[3] = x1 + y1 + z0;
        idx[4] = x0 + y0 + z1; idx[5] = x1 + y0 + z1;
        idx[6] = x0 + y1 + z1; idx[7] = x1 + y1 + z1;
    } else {
        uint32_t hx0 = gx,               hx1 = gx + 1u;
        uint32_t hy0 = gy * 2654435761u, hy1 = hy0 + 2654435761u;
        uint32_t hz0 = gz * 805459861u,  hz1 = hz0 + 805459861u;
        idx[0] = (hx0 ^ hy0 ^ hz0) & HASH_MASK; idx[1] = (hx1 ^ hy0 ^ hz0) & HASH_MASK;
        idx[2] = (hx0 ^ hy1 ^ hz0) & HASH_MASK; idx[3] = (hx1 ^ hy1 ^ hz0) & HASH_MASK;
        idx[4] = (hx0 ^ hy0 ^ hz1) & HASH_MASK; idx[5] = (hx1 ^ hy0 ^ hz1) & HASH_MASK;
        idx[6] = (hx0 ^ hy1 ^ hz1) & HASH_MASK; idx[7] = (hx1 ^ hy1 ^ hz1) & HASH_MASK;
    }
}

__device__ __forceinline__ void load8(float4* f, const float4* tab, const uint32_t* idx)
{
#pragma unroll
    for (int k = 0; k < 8; ++k) f[k] = __ldg(tab + idx[k]);
}

__device__ __forceinline__ float4 blend8(const float4* f, float3 w)
{
    float ux = 1.0f - w.x, uy = 1.0f - w.y, uz = 1.0f - w.z;
    float w0 = ux * uy * uz, w1 = w.x * uy * uz;
    float w2 = ux * w.y * uz, w3 = w.x * w.y * uz;
    float w4 = ux * uy * w.z, w5 = w.x * uy * w.z;
    float w6 = ux * w.y * w.z, w7 = w.x * w.y * w.z;
    float4 a;
    a.x = f[0].x*w0 + f[1].x*w1 + f[2].x*w2 + f[3].x*w3 + f[4].x*w4 + f[5].x*w5 + f[6].x*w6 + f[7].x*w7;
    a.y = f[0].y*w0 + f[1].y*w1 + f[2].y*w2 + f[3].y*w3 + f[4].y*w4 + f[5].y*w5 + f[6].y*w6 + f[7].y*w7;
    a.z = f[0].z*w0 + f[1].z*w1 + f[2].z*w2 + f[3].z*w3 + f[4].z*w4 + f[5].z*w5 + f[6].z*w6 + f[7].z*w7;
    a.w = f[0].w*w0 + f[1].w*w1 + f[2].w*w2 + f[3].w*w3 + f[4].w*w4 + f[5].w*w5 + f[6].w*w6 + f[7].w*w7;
    return a;
}

__global__ void __launch_bounds__(256)
k4_encode(const float* __restrict__ table, float4* __restrict__ out, int n)
{
    __shared__ float sbuf[8][32][28];   // 8 warps x 32 rows x 96B (stride 112B)

    int j = blockIdx.x * blockDim.x + threadIdx.x;
    const int lane = threadIdx.x & 31;
    const int w    = threadIdx.x >> 5;
    bool active = (j < n);

    uint32_t orig = active ? d_perm[j] : 0u;
    float4 c = ldcs_f4(&d_coords[orig]);
    const float cx = c.x, cy = c.y, cz = c.z;

    const float4* tb = reinterpret_cast<const float4*>(table);
    float* srow = &sbuf[w][lane][0];

    uint32_t ia[8], ib[8];
    float3 wa, wb;
    float4 A[8], B[8];

    // 2-stage software pipeline over levels 5..0
    level_idx<5>(cx, cy, cz, ia, wa); load8(A, tb + 5u * HASHMAP_SIZE, ia);
    level_idx<4>(cx, cy, cz, ib, wb); load8(B, tb + 4u * HASHMAP_SIZE, ib);
    *reinterpret_cast<float4*>(srow + 5 * 4) = blend8(A, wa);
    level_idx<3>(cx, cy, cz, ia, wa); load8(A, tb + 3u * HASHMAP_SIZE, ia);
    *reinterpret_cast<float4*>(srow + 4 * 4) = blend8(B, wb);
    level_idx<2>(cx, cy, cz, ib, wb); load8(B, tb + 2u * HASHMAP_SIZE, ib);
    *reinterpret_cast<float4*>(srow + 3 * 4) = blend8(A, wa);
    level_idx<1>(cx, cy, cz, ia, wa); load8(A, tb + 1u * HASHMAP_SIZE, ia);
    *reinterpret_cast<float4*>(srow + 2 * 4) = blend8(B, wb);
    level_idx<0>(cx, cy, cz, ib, wb); load8(B, tb, ib);
    *reinterpret_cast<float4*>(srow + 1 * 4) = blend8(A, wa);
    *reinterpret_cast<float4*>(srow + 0 * 4) = blend8(B, wb);

    __syncwarp();

    const unsigned fullmask = 0xffffffffu;
    unsigned m = __ballot_sync(fullmask, active);
    bool warp_full = (m == 0xffffffffu);

    if (warp_full) {
#pragma unroll
        for (int it = 0; it < 7; ++it) {
            int f  = it * 30 + lane;
            int fc = f < 192 ? f : 191;          // clamp for uniform shfl
            int r  = fc / 6;
            int L  = fc - r * 6;
            float4 v = *reinterpret_cast<float4*>(&sbuf[w][r][L * 4]);
            uint32_t org_r = __shfl_sync(fullmask, orig, r);
            if (lane < 30 && f < 192)
                stcs_f4(&out[(size_t)org_r * 6 + L], v);
        }
    } else if (active) {
        float4* orow = out + (size_t)orig * 6;
#pragma unroll
        for (int L = 0; L < N_LEVELS; ++L)
            stcs_f4(&orow[L], *reinterpret_cast<float4*>(srow + L * 4));
    }
}

// ---------------------------------------------------------------- launch
extern "C" void kernel_launch(void* const* d_in, const int* in_sizes, int n_in,
                              void* d_out, int out_size)
{
    const float* view_dirs   = (const float*)d_in[0];
    const float* ray_origins = (const float*)d_in[1];
    const float* table       = (const float*)d_in[2];
    float4* out              = (float4*)d_out;

    int n = in_sizes[0] / 3;
    int threads = 256;
    int blocks  = (n + threads - 1) / threads;

    k0_zero<<<NBINS / 4 / 256, 256>>>();
    k1_bin<<<blocks, threads>>>(view_dirs, ray_origins, n);
    k2a_scan<<<SCAN_BLOCKS, 1024>>>();
    k2b_scan<<<1, 128>>>();
    k3_scatter<<<blocks, threads>>>(n);
    k4_encode<<<blocks, threads>>>(table, out, n);
}

// round 9
// speedup vs baseline: 1.0044x; 1.0044x over previous
#include <cuda_runtime.h>
#include <stdint.h>

#define N_RAYS   1048576
#define N_LEVELS 6
#define HASHMAP_SIZE (1u << 19)
#define HASH_MASK    (HASHMAP_SIZE - 1u)
#define SPHERE_R 500.0f

#define OCT_RES   512                      // 2D octahedral bins per axis
#define NBINS     (OCT_RES * OCT_RES)      // 262144
#define SCAN_CHUNK 2048
#define SCAN_BLOCKS (NBINS / SCAN_CHUNK)   // 128

__device__ uint32_t d_hist[NBINS];         // zero-init at load; k2a re-zeroes after use
__device__ uint32_t d_offsets[NBINS];      // chunk-local after k2a
__device__ uint32_t d_bsum[SCAN_BLOCKS];   // RAW chunk sums (k3 scans locally)
__device__ float4   d_coords[N_RAYS];
__device__ uint32_t d_bin[N_RAYS];
__device__ uint32_t d_perm[N_RAYS];

// ---------------------------------------------------------------- helpers
__device__ __forceinline__ uint32_t expand2(uint32_t v)
{
    v &= 0xFFFFu;
    v = (v | (v << 8)) & 0x00FF00FFu;
    v = (v | (v << 4)) & 0x0F0F0F0Fu;
    v = (v | (v << 2)) & 0x33333333u;
    v = (v | (v << 1)) & 0x55555555u;
    return v;
}

__device__ __forceinline__ float3 ray_coords(const float* __restrict__ dirs,
                                             const float* __restrict__ origs, int i)
{
    const float dx = dirs[3 * i + 0], dy = dirs[3 * i + 1], dz = dirs[3 * i + 2];
    const float ox = origs[3 * i + 0], oy = origs[3 * i + 1], oz = origs[3 * i + 2];
    float b    = 2.0f * (ox * dx + oy * dy + oz * dz);
    float c    = (ox * ox + oy * oy + oz * oz) - SPHERE_R * SPHERE_R;
    float disc = b * b - 4.0f * c;
    float t    = 0.5f * (sqrtf(fmaxf(disc, 0.0f)) - b);
    const float inv2R = 1.0f / (2.0f * SPHERE_R);
    float3 r;
    r.x = fminf(fmaxf((ox + t * dx + SPHERE_R) * inv2R, 0.0f), 1.0f);
    r.y = fminf(fmaxf((oy + t * dy + SPHERE_R) * inv2R, 0.0f), 1.0f);
    r.z = fminf(fmaxf((oz + t * dz + SPHERE_R) * inv2R, 0.0f), 1.0f);
    return r;
}

__device__ __forceinline__ void stcs_f4(float4* p, float4 v)
{
    asm volatile("st.global.cs.v4.f32 [%0], {%1,%2,%3,%4};"
                 :: "l"(p), "f"(v.x), "f"(v.y), "f"(v.z), "f"(v.w) : "memory");
}
__device__ __forceinline__ void stcs_u32(uint32_t* p, uint32_t v)
{
    asm volatile("st.global.cs.u32 [%0], %1;" :: "l"(p), "r"(v) : "memory");
}
__device__ __forceinline__ float4 ldcs_f4(const float4* p)
{
    float4 v;
    asm volatile("ld.global.cs.v4.f32 {%0,%1,%2,%3}, [%4];"
                 : "=f"(v.x), "=f"(v.y), "=f"(v.z), "=f"(v.w) : "l"(p));
    return v;
}

// ---------------------------------------------------------------- K1: coords + octahedral Morton bin + histogram
__global__ void __launch_bounds__(256)
k1_bin(const float* __restrict__ dirs, const float* __restrict__ origs, int n)
{
    int i = blockIdx.x * blockDim.x + threadIdx.x;
    if (i >= n) return;
    float3 cc = ray_coords(dirs, origs, i);

    // unit direction (points lie on the sphere); octahedral map
    float px = 2.0f * cc.x - 1.0f;
    float py = 2.0f * cc.y - 1.0f;
    float pz = 2.0f * cc.z - 1.0f;
    float inv = 1.0f / (fabsf(px) + fabsf(py) + fabsf(pz));
    float u = px * inv, v = py * inv;
    if (pz < 0.0f) {
        float uu = (1.0f - fabsf(v)) * copysignf(1.0f, u);
        float vv = (1.0f - fabsf(u)) * copysignf(1.0f, v);
        u = uu; v = vv;
    }
    uint32_t bu = min((uint32_t)((u * 0.5f + 0.5f) * (float)OCT_RES), (uint32_t)(OCT_RES - 1));
    uint32_t bv = min((uint32_t)((v * 0.5f + 0.5f) * (float)OCT_RES), (uint32_t)(OCT_RES - 1));
    uint32_t bin = expand2(bu) | (expand2(bv) << 1);   // 18-bit Morton

    stcs_f4(&d_coords[i], make_float4(cc.x, cc.y, cc.z, 0.0f));
    stcs_u32(&d_bin[i], bin);
    atomicAdd(&d_hist[bin], 1u);
}

// ---------------------------------------------------------------- block scan helper (1024 threads)
__device__ __forceinline__ uint32_t block_incl_scan_1024(uint32_t v, uint32_t* wsum)
{
    const int lane = threadIdx.x & 31, wid = threadIdx.x >> 5;
    uint32_t x = v;
#pragma unroll
    for (int d = 1; d < 32; d <<= 1) {
        uint32_t y = __shfl_up_sync(0xffffffffu, x, d);
        if (lane >= d) x += y;
    }
    if (lane == 31) wsum[wid] = x;
    __syncthreads();
    if (wid == 0) {
        uint32_t s = wsum[lane];
        uint32_t t = s;
#pragma unroll
        for (int d = 1; d < 32; d <<= 1) {
            uint32_t y = __shfl_up_sync(0xffffffffu, t, d);
            if (lane >= d) t += y;
        }
        wsum[lane] = t - s;
    }
    __syncthreads();
    return x + wsum[wid];
}

// ---------------------------------------------------------------- K2a: per-chunk scan + re-zero hist
__global__ void __launch_bounds__(1024)
k2a_scan()
{
    __shared__ uint32_t wsum[32];
    const int base = blockIdx.x * SCAN_CHUNK;
    const int t = threadIdx.x;
    uint2 e = reinterpret_cast<const uint2*>(d_hist + base)[t];
    // re-zero hist for the next graph replay (zero-init covers the first run)
    reinterpret_cast<uint2*>(d_hist + base)[t] = make_uint2(0u, 0u);
    uint32_t s = e.x + e.y;
    uint32_t incl = block_incl_scan_1024(s, wsum);
    uint32_t excl = incl - s;
    reinterpret_cast<uint2*>(d_offsets + base)[t] = make_uint2(excl, excl + e.x);
    if (t == 1023) d_bsum[blockIdx.x] = incl;   // RAW chunk sum
}

// ---------------------------------------------------------------- K3: scatter; each block scans the 128 chunk sums locally
__global__ void __launch_bounds__(256)
k3_scatter(int n)
{
    __shared__ uint32_t s_base[SCAN_BLOCKS];   // exclusive prefix of chunk sums
    __shared__ uint32_t s_wsum[4];

    const int tid  = threadIdx.x;
    const int lane = tid & 31, wid = tid >> 5;

    // warps 0..3: scan 128 chunk sums (each warp handles 32)
    if (wid < 4) {
        uint32_t v = __ldg(&d_bsum[wid * 32 + lane]);
        uint32_t x = v;
#pragma unroll
        for (int d = 1; d < 32; d <<= 1) {
            uint32_t y = __shfl_up_sync(0xffffffffu, x, d);
            if (lane >= d) x += y;
        }
        if (lane == 31) s_wsum[wid] = x;
        __syncthreads();
        uint32_t add = 0;
#pragma unroll
        for (int k = 0; k < 4; ++k)
            if (k < wid) add += s_wsum[k];
        s_base[wid * 32 + lane] = x - v + add;   // exclusive
    } else {
        __syncthreads();
    }
    __syncthreads();

    int i = blockIdx.x * blockDim.x + tid;
    if (i >= n) return;
    uint32_t bin = d_bin[i];
    uint32_t pos = atomicAdd(&d_offsets[bin], 1u) + s_base[bin / SCAN_CHUNK];
    stcs_u32(&d_perm[pos], (uint32_t)i);
}

// ---------------------------------------------------------------- K4: pipelined coherent encode
template<int L>
__device__ __forceinline__ void level_idx(float cx, float cy, float cz,
                                          uint32_t* idx, float3& w)
{
    const float scale = (float)((16 << L) - 1);
    float px = cx * scale + 0.5f;
    float py = cy * scale + 0.5f;
    float pz = cz * scale + 0.5f;
    float fx = floorf(px), fy = floorf(py), fz = floorf(pz);
    w.x = px - fx; w.y = py - fy; w.z = pz - fz;
    uint32_t gx = (uint32_t)fx, gy = (uint32_t)fy, gz = (uint32_t)fz;

    if (L < 3) {
        const uint32_t r  = 16u << L;
        const uint32_t rm = r - 1u;
        uint32_t x0 = gx,            x1 = min(gx + 1u, rm);
        uint32_t y0 = gy * r,        y1 = min(gy + 1u, rm) * r;
        uint32_t z0 = gz * r * r,    z1 = min(gz + 1u, rm) * r * r;
        idx[0] = x0 + y0 + z0; idx[1] = x1 + y0 + z0;
        idx[2] = x0 + y1 + z0; idx[3] = x1 + y1 + z0;
        idx[4] = x0 + y0 + z1; idx[5] = x1 + y0 + z1;
        idx[6] = x0 + y1 + z1; idx[7] = x1 + y1 + z1;
    } else {
        uint32_t hx0 = gx,               hx1 = gx + 1u;
        uint32_t hy0 = gy * 2654435761u, hy1 = hy0 + 2654435761u;
        uint32_t hz0 = gz * 805459861u,  hz1 = hz0 + 805459861u;
        idx[0] = (hx0 ^ hy0 ^ hz0) & HASH_MASK; idx[1] = (hx1 ^ hy0 ^ hz0) & HASH_MASK;
        idx[2] = (hx0 ^ hy1 ^ hz0) & HASH_MASK; idx[3] = (hx1 ^ hy1 ^ hz0) & HASH_MASK;
        idx[4] = (hx0 ^ hy0 ^ hz1) & HASH_MASK; idx[5] = (hx1 ^ hy0 ^ hz1) & HASH_MASK;
        idx[6] = (hx0 ^ hy1 ^ hz1) & HASH_MASK; idx[7] = (hx1 ^ hy1 ^ hz1) & HASH_MASK;
    }
}

__device__ __forceinline__ void load8(float4* f, const float4* tab, const uint32_t* idx)
{
#pragma unroll
    for (int k = 0; k < 8; ++k) f[k] = __ldg(tab + idx[k]);
}

__device__ __forceinline__ float4 blend8(const float4* f, float3 w)
{
    float ux = 1.0f - w.x, uy = 1.0f - w.y, uz = 1.0f - w.z;
    float w0 = ux * uy * uz, w1 = w.x * uy * uz;
    float w2 = ux * w.y * uz, w3 = w.x * w.y * uz;
    float w4 = ux * uy * w.z, w5 = w.x * uy * w.z;
    float w6 = ux * w.y * w.z, w7 = w.x * w.y * w.z;
    float4 a;
    a.x = f[0].x*w0 + f[1].x*w1 + f[2].x*w2 + f[3].x*w3 + f[4].x*w4 + f[5].x*w5 + f[6].x*w6 + f[7].x*w7;
    a.y = f[0].y*w0 + f[1].y*w1 + f[2].y*w2 + f[3].y*w3 + f[4].y*w4 + f[5].y*w5 + f[6].y*w6 + f[7].y*w7;
    a.z = f[0].z*w0 + f[1].z*w1 + f[2].z*w2 + f[3].z*w3 + f[4].z*w4 + f[5].z*w5 + f[6].z*w6 + f[7].z*w7;
    a.w = f[0].w*w0 + f[1].w*w1 + f[2].w*w2 + f[3].w*w3 + f[4].w*w4 + f[5].w*w5 + f[6].w*w6 + f[7].w*w7;
    return a;
}

__global__ void __launch_bounds__(256)
k4_encode(const float* __restrict__ table, float4* __restrict__ out, int n)
{
    __shared__ float sbuf[8][32][28];   // 8 warps x 32 rows x 96B (stride 112B)

    int j = blockIdx.x * blockDim.x + threadIdx.x;
    const int lane = threadIdx.x & 31;
    const int w    = threadIdx.x >> 5;
    bool active = (j < n);

    uint32_t orig = active ? d_perm[j] : 0u;
    float4 c = ldcs_f4(&d_coords[orig]);
    const float cx = c.x, cy = c.y, cz = c.z;

    const float4* tb = reinterpret_cast<const float4*>(table);
    float* srow = &sbuf[w][lane][0];

    uint32_t ia[8], ib[8];
    float3 wa, wb;
    float4 A[8], B[8];

    // 2-stage software pipeline over levels 5..0
    level_idx<5>(cx, cy, cz, ia, wa); load8(A, tb + 5u * HASHMAP_SIZE, ia);
    level_idx<4>(cx, cy, cz, ib, wb); load8(B, tb + 4u * HASHMAP_SIZE, ib);
    *reinterpret_cast<float4*>(srow + 5 * 4) = blend8(A, wa);
    level_idx<3>(cx, cy, cz, ia, wa); load8(A, tb + 3u * HASHMAP_SIZE, ia);
    *reinterpret_cast<float4*>(srow + 4 * 4) = blend8(B, wb);
    level_idx<2>(cx, cy, cz, ib, wb); load8(B, tb + 2u * HASHMAP_SIZE, ib);
    *reinterpret_cast<float4*>(srow + 3 * 4) = blend8(A, wa);
    level_idx<1>(cx, cy, cz, ia, wa); load8(A, tb + 1u * HASHMAP_SIZE, ia);
    *reinterpret_cast<float4*>(srow + 2 * 4) = blend8(B, wb);
    level_idx<0>(cx, cy, cz, ib, wb); load8(B, tb, ib);
    *reinterpret_cast<float4*>(srow + 1 * 4) = blend8(A, wa);
    *reinterpret_cast<float4*>(srow + 0 * 4) = blend8(B, wb);

    __syncwarp();

    const unsigned fullmask = 0xffffffffu;
    unsigned m = __ballot_sync(fullmask, active);
    bool warp_full = (m == 0xffffffffu);

    if (warp_full) {
#pragma unroll
        for (int it = 0; it < 7; ++it) {
            int f  = it * 30 + lane;
            int fc = f < 192 ? f : 191;          // clamp for uniform shfl
            int r  = fc / 6;
            int L  = fc - r * 6;
            float4 v = *reinterpret_cast<float4*>(&sbuf[w][r][L * 4]);
            uint32_t org_r = __shfl_sync(fullmask, orig, r);
            if (lane < 30 && f < 192)
                stcs_f4(&out[(size_t)org_r * 6 + L], v);
        }
    } else if (active) {
        float4* orow = out + (size_t)orig * 6;
#pragma unroll
        for (int L = 0; L < N_LEVELS; ++L)
            stcs_f4(&orow[L], *reinterpret_cast<float4*>(srow + L * 4));
    }
}

// ---------------------------------------------------------------- launch
extern "C" void kernel_launch(void* const* d_in, const int* in_sizes, int n_in,
                              void* d_out, int out_size)
{
    const float* view_dirs   = (const float*)d_in[0];
    const float* ray_origins = (const float*)d_in[1];
    const float* table       = (const float*)d_in[2];
    float4* out              = (float4*)d_out;

    int n = in_sizes[0] / 3;
    int threads = 256;
    int blocks  = (n + threads - 1) / threads;

    k1_bin<<<blocks, threads>>>(view_dirs, ray_origins, n);
    k2a_scan<<<SCAN_BLOCKS, 1024>>>();
    k3_scatter<<<blocks, threads>>>(n);
    k4_encode<<<blocks, threads>>>(table, out, n);
}

// round 11
// speedup vs baseline: 1.1624x; 1.1574x over previous
#include <cuda_runtime.h>
#include <stdint.h>

#define N_RAYS   1048576
#define N_LEVELS 6
#define HASHMAP_SIZE (1u << 19)
#define HASH_MASK    (HASHMAP_SIZE - 1u)
#define SPHERE_R 500.0f

#define OCT_RES   512                      // 2D octahedral bins per axis
#define NBINS     (OCT_RES * OCT_RES)      // 262144
#define SCAN_CHUNK 2048
#define SCAN_BLOCKS (NBINS / SCAN_CHUNK)   // 128

__device__ uint32_t d_hist[NBINS];         // zero-init at load; k2a re-zeroes after use
__device__ uint32_t d_offsets[NBINS];      // chunk-local after k2a
__device__ uint32_t d_bsum[SCAN_BLOCKS];   // RAW chunk sums (k3 scans locally)
__device__ float4   d_sorted[N_RAYS];      // (cx,cy,cz, orig-as-bits), bin-sorted

// ---------------------------------------------------------------- helpers
__device__ __forceinline__ uint32_t expand2(uint32_t v)
{
    v &= 0xFFFFu;
    v = (v | (v << 8)) & 0x00FF00FFu;
    v = (v | (v << 4)) & 0x0F0F0F0Fu;
    v = (v | (v << 2)) & 0x33333333u;
    v = (v | (v << 1)) & 0x55555555u;
    return v;
}

__device__ __forceinline__ float3 ray_coords(const float* __restrict__ dirs,
                                             const float* __restrict__ origs, int i)
{
    const float dx = dirs[3 * i + 0], dy = dirs[3 * i + 1], dz = dirs[3 * i + 2];
    const float ox = origs[3 * i + 0], oy = origs[3 * i + 1], oz = origs[3 * i + 2];
    float b    = 2.0f * (ox * dx + oy * dy + oz * dz);
    float c    = (ox * ox + oy * oy + oz * oz) - SPHERE_R * SPHERE_R;
    float disc = b * b - 4.0f * c;
    float t    = 0.5f * (sqrtf(fmaxf(disc, 0.0f)) - b);
    const float inv2R = 1.0f / (2.0f * SPHERE_R);
    float3 r;
    r.x = fminf(fmaxf((ox + t * dx + SPHERE_R) * inv2R, 0.0f), 1.0f);
    r.y = fminf(fmaxf((oy + t * dy + SPHERE_R) * inv2R, 0.0f), 1.0f);
    r.z = fminf(fmaxf((oz + t * dz + SPHERE_R) * inv2R, 0.0f), 1.0f);
    return r;
}

// octahedral Morton bin of a coord triple (deterministic, shared by k1/k3)
__device__ __forceinline__ uint32_t oct_bin(float3 cc)
{
    float px = 2.0f * cc.x - 1.0f;
    float py = 2.0f * cc.y - 1.0f;
    float pz = 2.0f * cc.z - 1.0f;
    float inv = 1.0f / (fabsf(px) + fabsf(py) + fabsf(pz));
    float u = px * inv, v = py * inv;
    if (pz < 0.0f) {
        float uu = (1.0f - fabsf(v)) * copysignf(1.0f, u);
        float vv = (1.0f - fabsf(u)) * copysignf(1.0f, v);
        u = uu; v = vv;
    }
    uint32_t bu = min((uint32_t)((u * 0.5f + 0.5f) * (float)OCT_RES), (uint32_t)(OCT_RES - 1));
    uint32_t bv = min((uint32_t)((v * 0.5f + 0.5f) * (float)OCT_RES), (uint32_t)(OCT_RES - 1));
    return expand2(bu) | (expand2(bv) << 1);   // 18-bit Morton
}

__device__ __forceinline__ void stcs_f4(float4* p, float4 v)
{
    asm volatile("st.global.cs.v4.f32 [%0], {%1,%2,%3,%4};"
                 :: "l"(p), "f"(v.x), "f"(v.y), "f"(v.z), "f"(v.w) : "memory");
}
__device__ __forceinline__ float4 ldcs_f4(const float4* p)
{
    float4 v;
    asm volatile("ld.global.cs.v4.f32 {%0,%1,%2,%3}, [%4];"
                 : "=f"(v.x), "=f"(v.y), "=f"(v.z), "=f"(v.w) : "l"(p));
    return v;
}

// ---------------------------------------------------------------- K1: histogram only
__global__ void __launch_bounds__(256)
k1_bin(const float* __restrict__ dirs, const float* __restrict__ origs, int n)
{
    int i = blockIdx.x * blockDim.x + threadIdx.x;
    if (i >= n) return;
    uint32_t bin = oct_bin(ray_coords(dirs, origs, i));
    atomicAdd(&d_hist[bin], 1u);
}

// ---------------------------------------------------------------- block scan helper (1024 threads)
__device__ __forceinline__ uint32_t block_incl_scan_1024(uint32_t v, uint32_t* wsum)
{
    const int lane = threadIdx.x & 31, wid = threadIdx.x >> 5;
    uint32_t x = v;
#pragma unroll
    for (int d = 1; d < 32; d <<= 1) {
        uint32_t y = __shfl_up_sync(0xffffffffu, x, d);
        if (lane >= d) x += y;
    }
    if (lane == 31) wsum[wid] = x;
    __syncthreads();
    if (wid == 0) {
        uint32_t s = wsum[lane];
        uint32_t t = s;
#pragma unroll
        for (int d = 1; d < 32; d <<= 1) {
            uint32_t y = __shfl_up_sync(0xffffffffu, t, d);
            if (lane >= d) t += y;
        }
        wsum[lane] = t - s;
    }
    __syncthreads();
    return x + wsum[wid];
}

// ---------------------------------------------------------------- K2a: per-chunk scan + re-zero hist
__global__ void __launch_bounds__(1024)
k2a_scan()
{
    __shared__ uint32_t wsum[32];
    const int base = blockIdx.x * SCAN_CHUNK;
    const int t = threadIdx.x;
    uint2 e = reinterpret_cast<const uint2*>(d_hist + base)[t];
    // re-zero hist for the next graph replay (zero-init covers the first run)
    reinterpret_cast<uint2*>(d_hist + base)[t] = make_uint2(0u, 0u);
    uint32_t s = e.x + e.y;
    uint32_t incl = block_incl_scan_1024(s, wsum);
    uint32_t excl = incl - s;
    reinterpret_cast<uint2*>(d_offsets + base)[t] = make_uint2(excl, excl + e.x);
    if (t == 1023) d_bsum[blockIdx.x] = incl;   // RAW chunk sum
}

// ---------------------------------------------------------------- K3: recompute coords+bin, scatter sorted records
__global__ void __launch_bounds__(256)
k3_scatter(const float* __restrict__ dirs, const float* __restrict__ origs, int n)
{
    __shared__ uint32_t s_base[SCAN_BLOCKS];   // exclusive prefix of chunk sums
    __shared__ uint32_t s_wsum[4];

    const int tid  = threadIdx.x;
    const int lane = tid & 31, wid = tid >> 5;

    // warps 0..3: scan 128 chunk sums (each warp handles 32)
    if (wid < 4) {
        uint32_t v = __ldg(&d_bsum[wid * 32 + lane]);
        uint32_t x = v;
#pragma unroll
        for (int d = 1; d < 32; d <<= 1) {
            uint32_t y = __shfl_up_sync(0xffffffffu, x, d);
            if (lane >= d) x += y;
        }
        if (lane == 31) s_wsum[wid] = x;
        __syncthreads();
        uint32_t add = 0;
#pragma unroll
        for (int k = 0; k < 4; ++k)
            if (k < wid) add += s_wsum[k];
        s_base[wid * 32 + lane] = x - v + add;   // exclusive
    } else {
        __syncthreads();
    }
    __syncthreads();

    int i = blockIdx.x * blockDim.x + tid;
    if (i >= n) return;
    float3 cc = ray_coords(dirs, origs, i);
    uint32_t bin = oct_bin(cc);
    uint32_t pos = atomicAdd(&d_offsets[bin], 1u) + s_base[bin / SCAN_CHUNK];
    stcs_f4(&d_sorted[pos], make_float4(cc.x, cc.y, cc.z, __uint_as_float((uint32_t)i)));
}

// ---------------------------------------------------------------- K4: pipelined coherent encode
template<int L>
__device__ __forceinline__ void level_idx(float cx, float cy, float cz,
                                          uint32_t* idx, float3& w)
{
    const float scale = (float)((16 << L) - 1);
    float px = cx * scale + 0.5f;
    float py = cy * scale + 0.5f;
    float pz = cz * scale + 0.5f;
    float fx = floorf(px), fy = floorf(py), fz = floorf(pz);
    w.x = px - fx; w.y = py - fy; w.z = pz - fz;
    uint32_t gx = (uint32_t)fx, gy = (uint32_t)fy, gz = (uint32_t)fz;

    if (L < 3) {
        const uint32_t r  = 16u << L;
        const uint32_t rm = r - 1u;
        uint32_t x0 = gx,            x1 = min(gx + 1u, rm);
        uint32_t y0 = gy * r,        y1 = min(gy + 1u, rm) * r;
        uint32_t z0 = gz * r * r,    z1 = min(gz + 1u, rm) * r * r;
        idx[0] = x0 + y0 + z0; idx[1] = x1 + y0 + z0;
        idx[2] = x0 + y1 + z0; idx[3] = x1 + y1 + z0;
        idx[4] = x0 + y0 + z1; idx[5] = x1 + y0 + z1;
        idx[6] = x0 + y1 + z1; idx[7] = x1 + y1 + z1;
    } else {
        uint32_t hx0 = gx,               hx1 = gx + 1u;
        uint32_t hy0 = gy * 2654435761u, hy1 = hy0 + 2654435761u;
        uint32_t hz0 = gz * 805459861u,  hz1 = hz0 + 805459861u;
        idx[0] = (hx0 ^ hy0 ^ hz0) & HASH_MASK; idx[1] = (hx1 ^ hy0 ^ hz0) & HASH_MASK;
        idx[2] = (hx0 ^ hy1 ^ hz0) & HASH_MASK; idx[3] = (hx1 ^ hy1 ^ hz0) & HASH_MASK;
        idx[4] = (hx0 ^ hy0 ^ hz1) & HASH_MASK; idx[5] = (hx1 ^ hy0 ^ hz1) & HASH_MASK;
        idx[6] = (hx0 ^ hy1 ^ hz1) & HASH_MASK; idx[7] = (hx1 ^ hy1 ^ hz1) & HASH_MASK;
    }
}

__device__ __forceinline__ void load8(float4* f, const float4* tab, const uint32_t* idx)
{
#pragma unroll
    for (int k = 0; k < 8; ++k) f[k] = __ldg(tab + idx[k]);
}

__device__ __forceinline__ float4 blend8(const float4* f, float3 w)
{
    float ux = 1.0f - w.x, uy = 1.0f - w.y, uz = 1.0f - w.z;
    float w0 = ux * uy * uz, w1 = w.x * uy * uz;
    float w2 = ux * w.y * uz, w3 = w.x * w.y * uz;
    float w4 = ux * uy * w.z, w5 = w.x * uy * w.z;
    float w6 = ux * w.y * w.z, w7 = w.x * w.y * w.z;
    float4 a;
    a.x = f[0].x*w0 + f[1].x*w1 + f[2].x*w2 + f[3].x*w3 + f[4].x*w4 + f[5].x*w5 + f[6].x*w6 + f[7].x*w7;
    a.y = f[0].y*w0 + f[1].y*w1 + f[2].y*w2 + f[3].y*w3 + f[4].y*w4 + f[5].y*w5 + f[6].y*w6 + f[7].y*w7;
    a.z = f[0].z*w0 + f[1].z*w1 + f[2].z*w2 + f[3].z*w3 + f[4].z*w4 + f[5].z*w5 + f[6].z*w6 + f[7].z*w7;
    a.w = f[0].w*w0 + f[1].w*w1 + f[2].w*w2 + f[3].w*w3 + f[4].w*w4 + f[5].w*w5 + f[6].w*w6 + f[7].w*w7;
    return a;
}

__global__ void __launch_bounds__(256)
k4_encode(const float* __restrict__ table, float4* __restrict__ out, int n)
{
    __shared__ float sbuf[8][32][28];   // 8 warps x 32 rows x 96B (stride 112B)

    int j = blockIdx.x * blockDim.x + threadIdx.x;
    const int lane = threadIdx.x & 31;
    const int w    = threadIdx.x >> 5;
    bool active = (j < n);

    float4 c = ldcs_f4(&d_sorted[active ? j : 0]);   // coalesced
    uint32_t orig = __float_as_uint(c.w);
    const float cx = c.x, cy = c.y, cz = c.z;

    const float4* tb = reinterpret_cast<const float4*>(table);
    float* srow = &sbuf[w][lane][0];

    uint32_t ia[8], ib[8];
    float3 wa, wb;
    float4 A[8], B[8];

    // 2-stage software pipeline over levels 5..0
    level_idx<5>(cx, cy, cz, ia, wa); load8(A, tb + 5u * HASHMAP_SIZE, ia);
    level_idx<4>(cx, cy, cz, ib, wb); load8(B, tb + 4u * HASHMAP_SIZE, ib);
    *reinterpret_cast<float4*>(srow + 5 * 4) = blend8(A, wa);
    level_idx<3>(cx, cy, cz, ia, wa); load8(A, tb + 3u * HASHMAP_SIZE, ia);
    *reinterpret_cast<float4*>(srow + 4 * 4) = blend8(B, wb);
    level_idx<2>(cx, cy, cz, ib, wb); load8(B, tb + 2u * HASHMAP_SIZE, ib);
    *reinterpret_cast<float4*>(srow + 3 * 4) = blend8(A, wa);
    level_idx<1>(cx, cy, cz, ia, wa); load8(A, tb + 1u * HASHMAP_SIZE, ia);
    *reinterpret_cast<float4*>(srow + 2 * 4) = blend8(B, wb);
    level_idx<0>(cx, cy, cz, ib, wb); load8(B, tb, ib);
    *reinterpret_cast<float4*>(srow + 1 * 4) = blend8(A, wa);
    *reinterpret_cast<float4*>(srow + 0 * 4) = blend8(B, wb);

    __syncwarp();

    const unsigned fullmask = 0xffffffffu;
    unsigned m = __ballot_sync(fullmask, active);
    bool warp_full = (m == 0xffffffffu);

    if (warp_full) {
#pragma unroll
        for (int it = 0; it < 7; ++it) {
            int f  = it * 30 + lane;
            int fc = f < 192 ? f : 191;          // clamp for uniform shfl
            int r  = fc / 6;
            int L  = fc - r * 6;
            float4 v = *reinterpret_cast<float4*>(&sbuf[w][r][L * 4]);
            uint32_t org_r = __shfl_sync(fullmask, orig, r);
            if (lane < 30 && f < 192)
                stcs_f4(&out[(size_t)org_r * 6 + L], v);
        }
    } else if (active) {
        float4* orow = out + (size_t)orig * 6;
#pragma unroll
        for (int L = 0; L < N_LEVELS; ++L)
            stcs_f4(&orow[L], *reinterpret_cast<float4*>(srow + L * 4));
    }
}

// ---------------------------------------------------------------- launch
extern "C" void kernel_launch(void* const* d_in, const int* in_sizes, int n_in,
                              void* d_out, int out_size)
{
    const float* view_dirs   = (const float*)d_in[0];
    const float* ray_origins = (const float*)d_in[1];
    const float* table       = (const float*)d_in[2];
    float4* out              = (float4*)d_out;

    int n = in_sizes[0] / 3;
    int threads = 256;
    int blocks  = (n + threads - 1) / threads;

    k1_bin<<<blocks, threads>>>(view_dirs, ray_origins, n);
    k2a_scan<<<SCAN_BLOCKS, 1024>>>();
    k3_scatter<<<blocks, threads>>>(view_dirs, ray_origins, n);
    k4_encode<<<blocks, threads>>>(table, out, n);
}